// round 4
// baseline (speedup 1.0000x reference)
#include <cuda_runtime.h>
#include <cuda_bf16.h>
#include <stdint.h>

constexpr int Bc = 4, Hc = 16, Pp = 1024, Dd = 128;
constexpr int NELEM = Bc * Hc * Pp * Dd;   // 8388608
constexpr int BM = 32;                      // query rows per CTA

// ---- device scratch: silu'd q/k as bf16 hi/lo split ----
__device__ __nv_bfloat16 g_qhi[NELEM], g_qlo[NELEM], g_khi[NELEM], g_klo[NELEM];

// ---- smem layout (bytes) ----
constexpr int OFF_AH  = 0;        // 32 rows x 256B (swizzled)
constexpr int OFF_AL  = 8192;
constexpr int OFF_B   = 16384;    // 2 bufs x 64KB (hi 32KB + lo 32KB)
constexpr int BSLAB   = 65536;
constexpr int OFF_RS  = OFF_B + 2 * BSLAB;   // 16 warps x 32 rows x 4B = 2048
constexpr int OFF_INV = OFF_RS + 2048;       // 32 x 4B
constexpr int SMEM2   = OFF_INV + 128;       // 149632 B

// =================== helpers ===================
__device__ __forceinline__ uint32_t smem_u32(const void* p) {
    uint32_t a;
    asm("{ .reg .u64 t; cvta.to.shared.u64 t, %1; cvt.u32.u64 %0, t; }" : "=r"(a) : "l"(p));
    return a;
}
__device__ __forceinline__ void cpa16(uint32_t dst, const void* src) {
    asm volatile("cp.async.cg.shared.global [%0], [%1], 16;" :: "r"(dst), "l"(src));
}
__device__ __forceinline__ void cpa_commit() { asm volatile("cp.async.commit_group;" ::: "memory"); }
template<int N>
__device__ __forceinline__ void cpa_wait() { asm volatile("cp.async.wait_group %0;" :: "n"(N) : "memory"); }

__device__ __forceinline__ void ldsm4(uint32_t* r, uint32_t addr) {
    asm volatile("ldmatrix.sync.aligned.m8n8.x4.shared.b16 {%0,%1,%2,%3}, [%4];"
                 : "=r"(r[0]), "=r"(r[1]), "=r"(r[2]), "=r"(r[3]) : "r"(addr));
}
__device__ __forceinline__ void mma16816(float* d, const uint32_t* a, uint32_t b0, uint32_t b1) {
    asm volatile(
        "mma.sync.aligned.m16n8k16.row.col.f32.bf16.bf16.f32 "
        "{%0,%1,%2,%3}, {%4,%5,%6,%7}, {%8,%9}, {%0,%1,%2,%3};"
        : "+f"(d[0]), "+f"(d[1]), "+f"(d[2]), "+f"(d[3])
        : "r"(a[0]), "r"(a[1]), "r"(a[2]), "r"(a[3]), "r"(b0), "r"(b1));
}
__device__ __forceinline__ float silu_f(float x) {
    return x * (1.0f / (1.0f + __expf(-x)));
}
__device__ __forceinline__ uint32_t pack_bf2(__nv_bfloat16 a, __nv_bfloat16 b) {
    __nv_bfloat162 t(a, b);
    return *reinterpret_cast<uint32_t*>(&t);
}

// =================== Pass 1: silu + bf16 hi/lo split ===================
__global__ void __launch_bounds__(256)
silu_split_kernel(const float* __restrict__ q, const float* __restrict__ k)
{
    int j = blockIdx.x * 256 + threadIdx.x;
    float4 vq = ((const float4*)q)[j];
    float4 vk = ((const float4*)k)[j];

    float s0 = silu_f(vq.x), s1 = silu_f(vq.y), s2 = silu_f(vq.z), s3 = silu_f(vq.w);
    __nv_bfloat16 h0 = __float2bfloat16(s0), h1 = __float2bfloat16(s1),
                  h2 = __float2bfloat16(s2), h3 = __float2bfloat16(s3);
    __nv_bfloat16 l0 = __float2bfloat16(s0 - __bfloat162float(h0));
    __nv_bfloat16 l1 = __float2bfloat16(s1 - __bfloat162float(h1));
    __nv_bfloat16 l2 = __float2bfloat16(s2 - __bfloat162float(h2));
    __nv_bfloat16 l3 = __float2bfloat16(s3 - __bfloat162float(h3));
    ((uint2*)g_qhi)[j] = make_uint2(pack_bf2(h0, h1), pack_bf2(h2, h3));
    ((uint2*)g_qlo)[j] = make_uint2(pack_bf2(l0, l1), pack_bf2(l2, l3));

    s0 = silu_f(vk.x); s1 = silu_f(vk.y); s2 = silu_f(vk.z); s3 = silu_f(vk.w);
    h0 = __float2bfloat16(s0); h1 = __float2bfloat16(s1);
    h2 = __float2bfloat16(s2); h3 = __float2bfloat16(s3);
    l0 = __float2bfloat16(s0 - __bfloat162float(h0));
    l1 = __float2bfloat16(s1 - __bfloat162float(h1));
    l2 = __float2bfloat16(s2 - __bfloat162float(h2));
    l3 = __float2bfloat16(s3 - __bfloat162float(h3));
    ((uint2*)g_khi)[j] = make_uint2(pack_bf2(h0, h1), pack_bf2(h2, h3));
    ((uint2*)g_klo)[j] = make_uint2(pack_bf2(l0, l1), pack_bf2(l2, l3));
}

// =================== Pass 2: HMMA GEMM + fused softmax ===================
// 512 threads = 16 warps. Warp w owns ALL 32 rows x keys [w*64, w*64+64).
// Stream over 8 d-slabs (16 dims x 1024 keys, hi+lo), double-buffered.
__global__ void __launch_bounds__(512, 1)
attn_mma_kernel(const float* __restrict__ scale_p, float* __restrict__ out)
{
    extern __shared__ char smem[];
    const uint32_t sb = smem_u32(smem);
    const int tid = threadIdx.x, lane = tid & 31, w = tid >> 5;
    const int mtile = blockIdx.x, bh = blockIdx.y;
    const float sc = scale_p[0];

    const char* khB = (const char*)g_khi + (size_t)bh * Pp * 256;
    const char* klB = (const char*)g_klo + (size_t)bh * Pp * 256;

    // ---- A tile (32 rows x 128 bf16, hi+lo), swizzled chunks ----
    {
        int row = tid >> 4, c = tid & 15;
        size_t g = ((size_t)(bh * Pp + mtile * BM) + row) * 256 + c * 16;
        uint32_t off = row * 256 + (((c ^ (row & 7)) & 15) << 4);
        cpa16(sb + OFF_AH + off, (const char*)g_qhi + g);
        cpa16(sb + OFF_AL + off, (const char*)g_qlo + g);
    }

    auto pfB = [&](int s) {
        uint32_t dst = sb + OFF_B + (s & 1) * BSLAB;
        #pragma unroll
        for (int ii = 0; ii < 4; ++ii) {
            int idx  = tid + ii * 512;       // (key, half)
            int key  = idx >> 1, half = idx & 1;
            uint32_t o = key * 32 + half * 16;
            size_t gsrc = (size_t)key * 256 + s * 32 + half * 16;
            cpa16(dst + o,         khB + gsrc);
            cpa16(dst + 32768 + o, klB + gsrc);
        }
        cpa_commit();
    };
    pfB(0);   // group 0 includes A
    pfB(1);

    // ---- fragment addressing ----
    const int lm = lane >> 3, lr = lane & 7;
    // A: m0 rows0-7/k0-7, m1 rows8-15/k0-7, m2 rows0-7/k8-15, m3 rows8-15/k8-15
    const int amsel = lm & 1, amc = lm >> 1;
    uint32_t arow256[2]; int ax[2];
    #pragma unroll
    for (int rg = 0; rg < 2; ++rg) {
        int r = rg * 16 + (amsel << 3) + lr;
        arow256[rg] = (uint32_t)r * 256;
        ax[rg] = r & 7;
    }
    // B: m0 keys0-7/k0-7, m1 keys0-7/k8-15, m2 keys8-15/k0-7, m3 keys8-15/k8-15
    const uint32_t bofs = (uint32_t)w * 2048 +
                          (uint32_t)((((lm >> 1) << 3) + lr) * 32) + (uint32_t)((lm & 1) << 4);

    float acc[2][8][4];
    #pragma unroll
    for (int rg = 0; rg < 2; ++rg)
        #pragma unroll
        for (int cb = 0; cb < 8; ++cb)
            #pragma unroll
            for (int j = 0; j < 4; ++j) acc[rg][cb][j] = 0.0f;

    cpa_wait<1>(); __syncthreads();   // A + slab 0 ready

    #pragma unroll
    for (int s = 0; s < 8; ++s) {
        const uint32_t bb = sb + OFF_B + (s & 1) * BSLAB;

        uint32_t ah[2][4], al[2][4];
        #pragma unroll
        for (int rg = 0; rg < 2; ++rg) {
            uint32_t c = (uint32_t)(2 * s + amc);
            uint32_t aoff = arow256[rg] + ((((c ^ (uint32_t)ax[rg]) & 15)) << 4);
            ldsm4(ah[rg], sb + OFF_AH + aoff);
            ldsm4(al[rg], sb + OFF_AL + aoff);
        }

        #pragma unroll
        for (int kg = 0; kg < 4; ++kg) {
            uint32_t bh4[4], bl4[4];
            ldsm4(bh4, bb + kg * 512 + bofs);
            ldsm4(bl4, bb + 32768 + kg * 512 + bofs);
            #pragma unroll
            for (int rg = 0; rg < 2; ++rg) {
                float* c0 = acc[rg][kg * 2];
                float* c1 = acc[rg][kg * 2 + 1];
                mma16816(c0, ah[rg], bh4[0], bh4[1]);
                mma16816(c1, ah[rg], bh4[2], bh4[3]);
                mma16816(c0, ah[rg], bl4[0], bl4[1]);
                mma16816(c1, ah[rg], bl4[2], bl4[3]);
                mma16816(c0, al[rg], bh4[0], bh4[1]);
                mma16816(c1, al[rg], bh4[2], bh4[3]);
            }
        }

        __syncthreads();               // everyone done reading buf s&1
        if (s + 2 < 8) pfB(s + 2);     // overwrite buf s&1 with slab s+2
        if (s < 7) {
            if (s + 2 < 8) { cpa_wait<1>(); } else { cpa_wait<0>(); }
            __syncthreads();           // slab s+1 visible to all
        }
    }

    // ---- exp ----
    #pragma unroll
    for (int rg = 0; rg < 2; ++rg)
        #pragma unroll
        for (int cb = 0; cb < 8; ++cb)
            #pragma unroll
            for (int j = 0; j < 4; ++j)
                acc[rg][cb][j] = __expf(sc * acc[rg][cb][j]);

    // ---- row sums over this warp's 64 keys ----
    float slo[2] = {0.f, 0.f}, shi[2] = {0.f, 0.f};
    #pragma unroll
    for (int rg = 0; rg < 2; ++rg)
        #pragma unroll
        for (int cb = 0; cb < 8; ++cb) {
            slo[rg] += acc[rg][cb][0] + acc[rg][cb][1];
            shi[rg] += acc[rg][cb][2] + acc[rg][cb][3];
        }
    #pragma unroll
    for (int o = 1; o < 4; o <<= 1) {
        slo[0] += __shfl_xor_sync(0xFFFFFFFFu, slo[0], o);
        slo[1] += __shfl_xor_sync(0xFFFFFFFFu, slo[1], o);
        shi[0] += __shfl_xor_sync(0xFFFFFFFFu, shi[0], o);
        shi[1] += __shfl_xor_sync(0xFFFFFFFFu, shi[1], o);
    }
    float* rs  = (float*)(smem + OFF_RS);
    float* inv = (float*)(smem + OFF_INV);
    const int r8 = lane >> 2;
    if ((lane & 3) == 0) {
        rs[w * 32 + r8]          = slo[0];
        rs[w * 32 + 8 + r8]      = shi[0];
        rs[w * 32 + 16 + r8]     = slo[1];
        rs[w * 32 + 24 + r8]     = shi[1];
    }
    __syncthreads();
    if (tid < 32) {
        float t = 0.0f;
        #pragma unroll
        for (int ww = 0; ww < 16; ++ww) t += rs[ww * 32 + tid];
        inv[tid] = 1.0f / t;
    }
    __syncthreads();

    // ---- normalized stores ----
    const float i_lo[2] = { inv[r8],      inv[16 + r8] };
    const float i_hi[2] = { inv[8 + r8],  inv[24 + r8] };
    #pragma unroll
    for (int rg = 0; rg < 2; ++rg) {
        size_t rowlo = (size_t)bh * Pp + mtile * BM + rg * 16 + r8;
        float* plo = out + rowlo * Pp + w * 64 + 2 * (lane & 3);
        float* phi = plo + 8ull * Pp;
        #pragma unroll
        for (int cb = 0; cb < 8; ++cb) {
            float2 v;
            v.x = acc[rg][cb][0] * i_lo[rg];
            v.y = acc[rg][cb][1] * i_lo[rg];
            *(float2*)(plo + cb * 8) = v;
            v.x = acc[rg][cb][2] * i_hi[rg];
            v.y = acc[rg][cb][3] * i_hi[rg];
            *(float2*)(phi + cb * 8) = v;
        }
    }
}

// =================== launch ===================
extern "C" void kernel_launch(void* const* d_in, const int* in_sizes, int n_in,
                              void* d_out, int out_size)
{
    const float* q     = (const float*)d_in[0];
    const float* k     = (const float*)d_in[1];
    const float* scale = (const float*)d_in[2];
    float* out = (float*)d_out;

    silu_split_kernel<<<NELEM / 4 / 256, 256>>>(q, k);

    cudaFuncSetAttribute(attn_mma_kernel,
                         cudaFuncAttributeMaxDynamicSharedMemorySize, SMEM2);
    dim3 grid(Pp / BM, Bc * Hc);  // (32, 64)
    attn_mma_kernel<<<grid, 512, SMEM2>>>(scale, out);
}

// round 5
// speedup vs baseline: 1.5584x; 1.5584x over previous
#include <cuda_runtime.h>
#include <cuda_fp16.h>
#include <stdint.h>

constexpr int Bc = 4, Hc = 16, Pp = 1024, Dd = 128;
constexpr int NELEM = Bc * Hc * Pp * Dd;   // 8388608
constexpr int BM = 32;       // query rows per CTA
constexpr int TN = 128;      // keys per tile
constexpr int NT = Pp / TN;  // 8 tiles

// ---- device scratch: silu'd q (fp16 hi+lo) and k (fp16) ----
__device__ __half g_qhi[NELEM], g_qlo[NELEM], g_khi[NELEM];

// ---- smem layout (bytes) ----
constexpr int OFF_AH  = 0;            // 32 rows x 256B (swizzled)
constexpr int OFF_AL  = 8192;
constexpr int OFF_B   = 16384;        // 3 bufs x 32KB (K hi only)
constexpr int BBUF    = 32768;
constexpr int OFF_RS  = OFF_B + 3 * BBUF;  // 16 warps x 32 rows x 4B
constexpr int OFF_INV = OFF_RS + 2048;     // 32 x 4B
constexpr int SMEM2   = OFF_INV + 128;     // 116864 B

// =================== helpers ===================
__device__ __forceinline__ uint32_t smem_u32(const void* p) {
    uint32_t a;
    asm("{ .reg .u64 t; cvta.to.shared.u64 t, %1; cvt.u32.u64 %0, t; }" : "=r"(a) : "l"(p));
    return a;
}
__device__ __forceinline__ void cpa16(uint32_t dst, const void* src) {
    asm volatile("cp.async.cg.shared.global [%0], [%1], 16;" :: "r"(dst), "l"(src));
}
__device__ __forceinline__ void cpa_commit() { asm volatile("cp.async.commit_group;" ::: "memory"); }
template<int N>
__device__ __forceinline__ void cpa_wait() { asm volatile("cp.async.wait_group %0;" :: "n"(N) : "memory"); }

__device__ __forceinline__ void ldsm4(uint32_t* r, uint32_t addr) {
    asm volatile("ldmatrix.sync.aligned.m8n8.x4.shared.b16 {%0,%1,%2,%3}, [%4];"
                 : "=r"(r[0]), "=r"(r[1]), "=r"(r[2]), "=r"(r[3]) : "r"(addr));
}
__device__ __forceinline__ void mma16816(float* d, const uint32_t* a, uint32_t b0, uint32_t b1) {
    asm volatile(
        "mma.sync.aligned.m16n8k16.row.col.f32.f16.f16.f32 "
        "{%0,%1,%2,%3}, {%4,%5,%6,%7}, {%8,%9}, {%0,%1,%2,%3};"
        : "+f"(d[0]), "+f"(d[1]), "+f"(d[2]), "+f"(d[3])
        : "r"(a[0]), "r"(a[1]), "r"(a[2]), "r"(a[3]), "r"(b0), "r"(b1));
}
__device__ __forceinline__ float silu_f(float x) {
    return x * (1.0f / (1.0f + __expf(-x)));
}
__device__ __forceinline__ uint32_t pack_h2(__half a, __half b) {
    __half2 t(a, b);
    return *reinterpret_cast<uint32_t*>(&t);
}

// =================== Pass 1: silu + fp16 (q split hi/lo, k hi) ===================
__global__ void __launch_bounds__(256)
silu_split_kernel(const float* __restrict__ q, const float* __restrict__ k)
{
    int j = blockIdx.x * 256 + threadIdx.x;   // float4 group index
    float4 vq = ((const float4*)q)[j];
    float4 vk = ((const float4*)k)[j];

    float s0 = silu_f(vq.x), s1 = silu_f(vq.y), s2 = silu_f(vq.z), s3 = silu_f(vq.w);
    __half h0 = __float2half(s0), h1 = __float2half(s1),
           h2 = __float2half(s2), h3 = __float2half(s3);
    __half l0 = __float2half(s0 - __half2float(h0));
    __half l1 = __float2half(s1 - __half2float(h1));
    __half l2 = __float2half(s2 - __half2float(h2));
    __half l3 = __float2half(s3 - __half2float(h3));
    ((uint2*)g_qhi)[j] = make_uint2(pack_h2(h0, h1), pack_h2(h2, h3));
    ((uint2*)g_qlo)[j] = make_uint2(pack_h2(l0, l1), pack_h2(l2, l3));

    s0 = silu_f(vk.x); s1 = silu_f(vk.y); s2 = silu_f(vk.z); s3 = silu_f(vk.w);
    ((uint2*)g_khi)[j] = make_uint2(
        pack_h2(__float2half(s0), __float2half(s1)),
        pack_h2(__float2half(s2), __float2half(s3)));
}

// =================== Pass 2: HMMA GEMM + fused softmax ===================
// 512 threads = 16 warps. Warp w: row band wb=w&1 (16 rows), col band wc=w>>1
// (16 keys of each 128-key tile). Scores stay in acc[8][8] registers.
__global__ void __launch_bounds__(512, 1)
attn_mma_kernel(const float* __restrict__ scale_p, float* __restrict__ out)
{
    extern __shared__ char smem[];
    const uint32_t sb = smem_u32(smem);
    const int tid = threadIdx.x, lane = tid & 31, w = tid >> 5;
    const int wb = w & 1, wc = w >> 1;
    const int mtile = blockIdx.x, bh = blockIdx.y;
    const float sc = scale_p[0];

    // ---- A tile (32 rows x 128 fp16, hi+lo), swizzled 16B chunks ----
    {
        int row = tid >> 4, c = tid & 15;
        size_t g = ((size_t)(bh * Pp + mtile * BM) + row) * 256 + c * 16;
        uint32_t off = row * 256 + (((c ^ (row & 7)) & 15) << 4);
        cpa16(sb + OFF_AH + off, (const char*)g_qhi + g);
        cpa16(sb + OFF_AL + off, (const char*)g_qlo + g);
    }

    const char* khB = (const char*)g_khi + (size_t)bh * Pp * 256;
    auto pfB = [&](int t) {
        uint32_t dst = sb + OFF_B + (t % 3) * BBUF;
        const char* src = khB + (size_t)(t * TN) * 256;
        #pragma unroll
        for (int i = 0; i < 4; ++i) {
            int idx = tid + i * 512;
            int row = idx >> 4, c = idx & 15;
            uint32_t off = row * 256 + (((c ^ (row & 7)) & 15) << 4);
            cpa16(dst + off, src + row * 256 + c * 16);
        }
        cpa_commit();
    };
    pfB(0);  // group 0 = A + B0
    pfB(1);
    pfB(2);

    // ---- fragment addressing ----
    const int lm = lane >> 3, lr = lane & 7;
    // A: m0 rows0-7/k0-7, m1 rows8-15/k0-7, m2 rows0-7/k8-15, m3 rows8-15/k8-15
    const int arow = wb * 16 + ((lm & 1) << 3) + lr;
    const uint32_t arow256 = (uint32_t)arow * 256;
    const int ax7 = arow & 7, amc = lm >> 1;
    // B: m0 keys0-7/k0-7, m1 keys0-7/k8-15, m2 keys8-15/k0-7, m3 keys8-15/k8-15
    const int brow = wc * 16 + ((lm >> 1) << 3) + lr;
    const uint32_t brow256 = (uint32_t)brow * 256;
    const int bx7 = brow & 7, bmc = lm & 1;

    float acc[NT][8];
    #pragma unroll
    for (int t = 0; t < NT; ++t)
        #pragma unroll
        for (int j = 0; j < 8; ++j) acc[t][j] = 0.0f;

    #pragma unroll
    for (int t = 0; t < NT; ++t) {
        if (t < 6) cpa_wait<2>(); else if (t == 6) cpa_wait<1>(); else cpa_wait<0>();
        __syncthreads();

        const uint32_t Bh = sb + OFF_B + (t % 3) * BBUF;

        #pragma unroll
        for (int ks = 0; ks < 8; ++ks) {
            uint32_t ah[4], al[4], bh4[4];
            uint32_t ac = (uint32_t)((((2 * ks + amc) ^ ax7) & 15) << 4);
            ldsm4(ah, sb + OFF_AH + arow256 + ac);
            ldsm4(al, sb + OFF_AL + arow256 + ac);
            uint32_t bc = (uint32_t)((((2 * ks + bmc) ^ bx7) & 15) << 4);
            ldsm4(bh4, Bh + brow256 + bc);

            mma16816(&acc[t][0], ah, bh4[0], bh4[1]);
            mma16816(&acc[t][4], ah, bh4[2], bh4[3]);
            mma16816(&acc[t][0], al, bh4[0], bh4[1]);
            mma16816(&acc[t][4], al, bh4[2], bh4[3]);
        }
        __syncthreads();
        if (t + 3 < NT) pfB(t + 3);
    }

    // ---- exp ----
    #pragma unroll
    for (int t = 0; t < NT; ++t)
        #pragma unroll
        for (int j = 0; j < 8; ++j) acc[t][j] = __expf(sc * acc[t][j]);

    // ---- row sums (rows wb*16 + lane/4 and +8) ----
    float s0 = 0.0f, s1 = 0.0f;
    #pragma unroll
    for (int t = 0; t < NT; ++t) {
        s0 += (acc[t][0] + acc[t][1]) + (acc[t][4] + acc[t][5]);
        s1 += (acc[t][2] + acc[t][3]) + (acc[t][6] + acc[t][7]);
    }
    #pragma unroll
    for (int o = 1; o < 4; o <<= 1) {
        s0 += __shfl_xor_sync(0xFFFFFFFFu, s0, o);
        s1 += __shfl_xor_sync(0xFFFFFFFFu, s1, o);
    }
    float* rs  = (float*)(smem + OFF_RS);
    float* inv = (float*)(smem + OFF_INV);
    const int g8 = lane >> 2;
    if ((lane & 3) == 0) {
        rs[wc * 32 + wb * 16 + g8]     = s0;
        rs[wc * 32 + wb * 16 + 8 + g8] = s1;
    }
    __syncthreads();
    if (tid < 32) {
        float tot = 0.0f;
        #pragma unroll
        for (int cb = 0; cb < 8; ++cb) tot += rs[cb * 32 + tid];
        inv[tid] = 1.0f / tot;
    }
    __syncthreads();
    const float i0 = inv[wb * 16 + g8];
    const float i1 = inv[wb * 16 + 8 + g8];

    // ---- normalized stores ----
    const int r0 = mtile * BM + wb * 16 + g8;
    float* ob0 = out + ((size_t)bh * Pp + r0) * Pp + wc * 16 + 2 * (lane & 3);
    float* ob1 = ob0 + 8ull * Pp;
    #pragma unroll
    for (int t = 0; t < NT; ++t) {
        int c0 = t * TN;
        float2 v;
        v.x = acc[t][0] * i0; v.y = acc[t][1] * i0; *(float2*)(ob0 + c0)     = v;
        v.x = acc[t][2] * i1; v.y = acc[t][3] * i1; *(float2*)(ob1 + c0)     = v;
        v.x = acc[t][4] * i0; v.y = acc[t][5] * i0; *(float2*)(ob0 + c0 + 8) = v;
        v.x = acc[t][6] * i1; v.y = acc[t][7] * i1; *(float2*)(ob1 + c0 + 8) = v;
    }
}

// =================== launch ===================
extern "C" void kernel_launch(void* const* d_in, const int* in_sizes, int n_in,
                              void* d_out, int out_size)
{
    const float* q     = (const float*)d_in[0];
    const float* k     = (const float*)d_in[1];
    const float* scale = (const float*)d_in[2];
    float* out = (float*)d_out;

    silu_split_kernel<<<NELEM / 4 / 256, 256>>>(q, k);

    cudaFuncSetAttribute(attn_mma_kernel,
                         cudaFuncAttributeMaxDynamicSharedMemorySize, SMEM2);
    dim3 grid(Pp / BM, Bc * Hc);  // (32, 64)
    attn_mma_kernel<<<grid, 512, SMEM2>>>(scale, out);
}

// round 6
// speedup vs baseline: 2.1887x; 1.4044x over previous
#include <cuda_runtime.h>
#include <cuda_fp16.h>
#include <stdint.h>

constexpr int Bc = 4, Hc = 16, Pp = 1024, Dd = 128;
constexpr int NELEM = Bc * Hc * Pp * Dd;   // 8388608
constexpr int BM = 32;       // query rows per CTA
constexpr int TN = 128;      // keys per tile
constexpr int NT = Pp / TN;  // 8 tiles

// ---- device scratch: silu'd q, k as fp16 ----
__device__ __half g_qh[NELEM], g_kh[NELEM];

// ---- smem layout (bytes) ----
constexpr int OFF_A   = 0;            // 32 rows x 256B (swizzled)
constexpr int OFF_B   = 8192;         // 3 bufs x 32KB
constexpr int BBUF    = 32768;
constexpr int OFF_RS  = OFF_B + 3 * BBUF;  // 8 colbands x 32 rows x 4B
constexpr int OFF_INV = OFF_RS + 2048;     // 32 x 4B
constexpr int SMEM2   = OFF_INV + 128;     // 108672 B

// =================== helpers ===================
__device__ __forceinline__ uint32_t smem_u32(const void* p) {
    uint32_t a;
    asm("{ .reg .u64 t; cvta.to.shared.u64 t, %1; cvt.u32.u64 %0, t; }" : "=r"(a) : "l"(p));
    return a;
}
__device__ __forceinline__ void cpa16(uint32_t dst, const void* src) {
    asm volatile("cp.async.cg.shared.global [%0], [%1], 16;" :: "r"(dst), "l"(src));
}
__device__ __forceinline__ void cpa_commit() { asm volatile("cp.async.commit_group;" ::: "memory"); }
template<int N>
__device__ __forceinline__ void cpa_wait() { asm volatile("cp.async.wait_group %0;" :: "n"(N) : "memory"); }

__device__ __forceinline__ void ldsm4(uint32_t* r, uint32_t addr) {
    asm volatile("ldmatrix.sync.aligned.m8n8.x4.shared.b16 {%0,%1,%2,%3}, [%4];"
                 : "=r"(r[0]), "=r"(r[1]), "=r"(r[2]), "=r"(r[3]) : "r"(addr));
}
__device__ __forceinline__ void mma16816(float* d, const uint32_t* a, uint32_t b0, uint32_t b1) {
    asm volatile(
        "mma.sync.aligned.m16n8k16.row.col.f32.f16.f16.f32 "
        "{%0,%1,%2,%3}, {%4,%5,%6,%7}, {%8,%9}, {%0,%1,%2,%3};"
        : "+f"(d[0]), "+f"(d[1]), "+f"(d[2]), "+f"(d[3])
        : "r"(a[0]), "r"(a[1]), "r"(a[2]), "r"(a[3]), "r"(b0), "r"(b1));
}
__device__ __forceinline__ float silu_f(float x) {
    return x * (1.0f / (1.0f + __expf(-x)));
}
__device__ __forceinline__ uint32_t pack_h2(__half a, __half b) {
    __half2 t(a, b);
    return *reinterpret_cast<uint32_t*>(&t);
}

// =================== Pass 1: silu -> fp16 ===================
__global__ void __launch_bounds__(256)
silu_split_kernel(const float* __restrict__ q, const float* __restrict__ k)
{
    int j = blockIdx.x * 256 + threadIdx.x;   // float4 group index
    float4 vq = ((const float4*)q)[j];
    float4 vk = ((const float4*)k)[j];

    ((uint2*)g_qh)[j] = make_uint2(
        pack_h2(__float2half(silu_f(vq.x)), __float2half(silu_f(vq.y))),
        pack_h2(__float2half(silu_f(vq.z)), __float2half(silu_f(vq.w))));
    ((uint2*)g_kh)[j] = make_uint2(
        pack_h2(__float2half(silu_f(vk.x)), __float2half(silu_f(vk.y))),
        pack_h2(__float2half(silu_f(vk.z)), __float2half(silu_f(vk.w))));
}

// =================== Pass 2: HMMA GEMM + fused softmax ===================
// 512 threads = 16 warps. Warp w: row band wb=w&1 (16 rows), col band wc=w>>1
// (16 keys of each 128-key tile). Scores in acc[8][8]; A frags hoisted to regs.
__global__ void __launch_bounds__(512, 1)
attn_mma_kernel(const float* __restrict__ scale_p, float* __restrict__ out)
{
    extern __shared__ char smem[];
    const uint32_t sb = smem_u32(smem);
    const int tid = threadIdx.x, lane = tid & 31, w = tid >> 5;
    const int wb = w & 1, wc = w >> 1;
    const int mtile = blockIdx.x, bh = blockIdx.y;
    const float sc = scale_p[0];

    // ---- A tile (32 rows x 128 fp16), swizzled 16B chunks ----
    if (tid < 512) {
        int row = tid >> 4, c = tid & 15;
        size_t g = ((size_t)(bh * Pp + mtile * BM) + row) * 256 + c * 16;
        uint32_t off = row * 256 + (((c ^ (row & 7)) & 15) << 4);
        cpa16(sb + OFF_A + off, (const char*)g_qh + g);
    }

    const char* khB = (const char*)g_kh + (size_t)bh * Pp * 256;
    auto pfB = [&](int t) {
        uint32_t dst = sb + OFF_B + (t % 3) * BBUF;
        const char* src = khB + (size_t)(t * TN) * 256;
        #pragma unroll
        for (int i = 0; i < 4; ++i) {
            int idx = tid + i * 512;
            int row = idx >> 4, c = idx & 15;
            uint32_t off = row * 256 + (((c ^ (row & 7)) & 15) << 4);
            cpa16(dst + off, src + row * 256 + c * 16);
        }
        cpa_commit();
    };
    pfB(0);  // group 0 = A + B0
    pfB(1);
    pfB(2);

    // ---- fragment addressing ----
    const int lm = lane >> 3, lr = lane & 7;
    // A: m0 rows0-7/k0-7, m1 rows8-15/k0-7, m2 rows0-7/k8-15, m3 rows8-15/k8-15
    const int arow = wb * 16 + ((lm & 1) << 3) + lr;
    const uint32_t arow256 = (uint32_t)arow * 256;
    const int ax7 = arow & 7, amc = lm >> 1;
    // B: m0 keys0-7/k0-7, m1 keys0-7/k8-15, m2 keys8-15/k0-7, m3 keys8-15/k8-15
    const int brow = wc * 16 + ((lm >> 1) << 3) + lr;
    const uint32_t brow256 = (uint32_t)brow * 256;
    const int bx7 = brow & 7, bmc = lm & 1;

    float acc[NT][8];
    #pragma unroll
    for (int t = 0; t < NT; ++t)
        #pragma unroll
        for (int j = 0; j < 8; ++j) acc[t][j] = 0.0f;

    uint32_t afrag[8][4];   // hoisted A fragments, one per ks

    #pragma unroll
    for (int t = 0; t < NT; ++t) {
        if (t < 6) cpa_wait<2>(); else if (t == 6) cpa_wait<1>(); else cpa_wait<0>();
        __syncthreads();

        if (t == 0) {
            #pragma unroll
            for (int ks = 0; ks < 8; ++ks) {
                uint32_t ac = (uint32_t)((((2 * ks + amc) ^ ax7) & 15) << 4);
                ldsm4(afrag[ks], sb + OFF_A + arow256 + ac);
            }
        }

        const uint32_t Bh = sb + OFF_B + (t % 3) * BBUF;

        #pragma unroll
        for (int ks = 0; ks < 8; ++ks) {
            uint32_t bh4[4];
            uint32_t bc = (uint32_t)((((2 * ks + bmc) ^ bx7) & 15) << 4);
            ldsm4(bh4, Bh + brow256 + bc);
            mma16816(&acc[t][0], afrag[ks], bh4[0], bh4[1]);
            mma16816(&acc[t][4], afrag[ks], bh4[2], bh4[3]);
        }
        __syncthreads();
        if (t + 3 < NT) pfB(t + 3);
    }

    // ---- exp ----
    #pragma unroll
    for (int t = 0; t < NT; ++t)
        #pragma unroll
        for (int j = 0; j < 8; ++j) acc[t][j] = __expf(sc * acc[t][j]);

    // ---- row sums (rows wb*16 + lane/4 and +8) ----
    float s0 = 0.0f, s1 = 0.0f;
    #pragma unroll
    for (int t = 0; t < NT; ++t) {
        s0 += (acc[t][0] + acc[t][1]) + (acc[t][4] + acc[t][5]);
        s1 += (acc[t][2] + acc[t][3]) + (acc[t][6] + acc[t][7]);
    }
    #pragma unroll
    for (int o = 1; o < 4; o <<= 1) {
        s0 += __shfl_xor_sync(0xFFFFFFFFu, s0, o);
        s1 += __shfl_xor_sync(0xFFFFFFFFu, s1, o);
    }
    float* rs  = (float*)(smem + OFF_RS);
    float* inv = (float*)(smem + OFF_INV);
    const int g8 = lane >> 2;
    if ((lane & 3) == 0) {
        rs[wc * 32 + wb * 16 + g8]     = s0;
        rs[wc * 32 + wb * 16 + 8 + g8] = s1;
    }
    __syncthreads();
    if (tid < 32) {
        float tot = 0.0f;
        #pragma unroll
        for (int cb = 0; cb < 8; ++cb) tot += rs[cb * 32 + tid];
        inv[tid] = 1.0f / tot;
    }
    __syncthreads();
    const float i0 = inv[wb * 16 + g8];
    const float i1 = inv[wb * 16 + 8 + g8];

    // ---- normalized stores ----
    const int r0 = mtile * BM + wb * 16 + g8;
    float* ob0 = out + ((size_t)bh * Pp + r0) * Pp + wc * 16 + 2 * (lane & 3);
    float* ob1 = ob0 + 8ull * Pp;
    #pragma unroll
    for (int t = 0; t < NT; ++t) {
        int c0 = t * TN;
        float2 v;
        v.x = acc[t][0] * i0; v.y = acc[t][1] * i0; *(float2*)(ob0 + c0)     = v;
        v.x = acc[t][2] * i1; v.y = acc[t][3] * i1; *(float2*)(ob1 + c0)     = v;
        v.x = acc[t][4] * i0; v.y = acc[t][5] * i0; *(float2*)(ob0 + c0 + 8) = v;
        v.x = acc[t][6] * i1; v.y = acc[t][7] * i1; *(float2*)(ob1 + c0 + 8) = v;
    }
}

// =================== launch ===================
extern "C" void kernel_launch(void* const* d_in, const int* in_sizes, int n_in,
                              void* d_out, int out_size)
{
    const float* q     = (const float*)d_in[0];
    const float* k     = (const float*)d_in[1];
    const float* scale = (const float*)d_in[2];
    float* out = (float*)d_out;

    silu_split_kernel<<<NELEM / 4 / 256, 256>>>(q, k);

    cudaFuncSetAttribute(attn_mma_kernel,
                         cudaFuncAttributeMaxDynamicSharedMemorySize, SMEM2);
    dim3 grid(Pp / BM, Bc * Hc);  // (32, 64)
    attn_mma_kernel<<<grid, 512, SMEM2>>>(scale, out);
}

// round 7
// speedup vs baseline: 2.2559x; 1.0307x over previous
#include <cuda_runtime.h>
#include <cuda_fp16.h>
#include <stdint.h>

constexpr int Bc = 4, Hc = 16, Pp = 1024, Dd = 128;
constexpr int NELEM = Bc * Hc * Pp * Dd;   // 8388608
constexpr int BM = 32;       // query rows per CTA
constexpr int TN = 128;      // keys per tile
constexpr int NT = Pp / TN;  // 8 tiles

// ---- device scratch: silu'd q, k as fp16 ----
__device__ __half g_qh[NELEM], g_kh[NELEM];

// ---- smem layout (bytes) ----
constexpr int OFF_A   = 0;            // 32 rows x 256B (swizzled)
constexpr int OFF_B   = 8192;         // 4 bufs x 32KB
constexpr int BBUF    = 32768;
constexpr int OFF_RS  = OFF_B + 4 * BBUF;  // 8 colbands x 32 rows x 4B
constexpr int OFF_INV = OFF_RS + 2048;     // 32 x 4B
constexpr int SMEM2   = OFF_INV + 128;     // 141440 B

// =================== helpers ===================
__device__ __forceinline__ uint32_t smem_u32(const void* p) {
    uint32_t a;
    asm("{ .reg .u64 t; cvta.to.shared.u64 t, %1; cvt.u32.u64 %0, t; }" : "=r"(a) : "l"(p));
    return a;
}
__device__ __forceinline__ void cpa16(uint32_t dst, const void* src) {
    asm volatile("cp.async.cg.shared.global [%0], [%1], 16;" :: "r"(dst), "l"(src));
}
__device__ __forceinline__ void cpa_commit() { asm volatile("cp.async.commit_group;" ::: "memory"); }
template<int N>
__device__ __forceinline__ void cpa_wait() { asm volatile("cp.async.wait_group %0;" :: "n"(N) : "memory"); }

__device__ __forceinline__ void ldsm4(uint32_t* r, uint32_t addr) {
    asm volatile("ldmatrix.sync.aligned.m8n8.x4.shared.b16 {%0,%1,%2,%3}, [%4];"
                 : "=r"(r[0]), "=r"(r[1]), "=r"(r[2]), "=r"(r[3]) : "r"(addr));
}
__device__ __forceinline__ void mma16816(float* d, const uint32_t* a, uint32_t b0, uint32_t b1) {
    asm volatile(
        "mma.sync.aligned.m16n8k16.row.col.f32.f16.f16.f32 "
        "{%0,%1,%2,%3}, {%4,%5,%6,%7}, {%8,%9}, {%0,%1,%2,%3};"
        : "+f"(d[0]), "+f"(d[1]), "+f"(d[2]), "+f"(d[3])
        : "r"(a[0]), "r"(a[1]), "r"(a[2]), "r"(a[3]), "r"(b0), "r"(b1));
}
__device__ __forceinline__ float silu_f(float x) {
    return x * (1.0f / (1.0f + __expf(-x)));
}
__device__ __forceinline__ uint32_t pack_h2(__half a, __half b) {
    __half2 t(a, b);
    return *reinterpret_cast<uint32_t*>(&t);
}

// =================== Pass 1: silu -> fp16 ===================
__global__ void __launch_bounds__(256)
silu_split_kernel(const float* __restrict__ q, const float* __restrict__ k)
{
    int j = blockIdx.x * 256 + threadIdx.x;   // float4 group index
    float4 vq = ((const float4*)q)[j];
    float4 vk = ((const float4*)k)[j];

    ((uint2*)g_qh)[j] = make_uint2(
        pack_h2(__float2half(silu_f(vq.x)), __float2half(silu_f(vq.y))),
        pack_h2(__float2half(silu_f(vq.z)), __float2half(silu_f(vq.w))));
    ((uint2*)g_kh)[j] = make_uint2(
        pack_h2(__float2half(silu_f(vk.x)), __float2half(silu_f(vk.y))),
        pack_h2(__float2half(silu_f(vk.z)), __float2half(silu_f(vk.w))));
}

// =================== Pass 2: HMMA GEMM + fused softmax ===================
// 512 threads = 16 warps. Warp w: row band wb=w&1 (16 rows), col band wc=w>>1
// (16 keys per 128-key tile). acc[8][8] in regs; A frags hoisted; B frags
// register-double-buffered; exp folded into the mainloop.
__global__ void __launch_bounds__(512, 1)
attn_mma_kernel(const float* __restrict__ scale_p, float* __restrict__ out)
{
    extern __shared__ char smem[];
    const uint32_t sb = smem_u32(smem);
    const int tid = threadIdx.x, lane = tid & 31, w = tid >> 5;
    const int wb = w & 1, wc = w >> 1;
    const int mtile = blockIdx.x, bh = blockIdx.y;
    const float sc = scale_p[0];

    // ---- A tile (32 rows x 128 fp16), swizzled 16B chunks (group 0) ----
    {
        int row = tid >> 4, c = tid & 15;
        size_t g = ((size_t)(bh * Pp + mtile * BM) + row) * 256 + c * 16;
        uint32_t off = row * 256 + (((c ^ (row & 7)) & 15) << 4);
        cpa16(sb + OFF_A + off, (const char*)g_qh + g);
    }

    const char* khB = (const char*)g_kh + (size_t)bh * Pp * 256;
    auto pfB = [&](int t) {
        uint32_t dst = sb + OFF_B + (t & 3) * BBUF;
        const char* src = khB + (size_t)(t * TN) * 256;
        #pragma unroll
        for (int i = 0; i < 4; ++i) {
            int idx = tid + i * 512;
            int row = idx >> 4, c = idx & 15;
            uint32_t off = row * 256 + (((c ^ (row & 7)) & 15) << 4);
            cpa16(dst + off, src + row * 256 + c * 16);
        }
        cpa_commit();
    };
    pfB(0);  // group 0 = A + B0
    pfB(1);
    pfB(2);

    // ---- fragment addressing ----
    const int lm = lane >> 3, lr = lane & 7;
    // A: m0 rows0-7/k0-7, m1 rows8-15/k0-7, m2 rows0-7/k8-15, m3 rows8-15/k8-15
    const int arow = wb * 16 + ((lm & 1) << 3) + lr;
    const uint32_t arow256 = (uint32_t)arow * 256;
    const int ax7 = arow & 7, amc = lm >> 1;
    // B: m0 keys0-7/k0-7, m1 keys0-7/k8-15, m2 keys8-15/k0-7, m3 keys8-15/k8-15
    const int brow = wc * 16 + ((lm >> 1) << 3) + lr;
    const uint32_t brow256 = (uint32_t)brow * 256;
    const int bx7 = brow & 7, bmc = lm & 1;

    float acc[NT][8];
    #pragma unroll
    for (int t = 0; t < NT; ++t)
        #pragma unroll
        for (int j = 0; j < 8; ++j) acc[t][j] = 0.0f;

    uint32_t afrag[8][4];   // hoisted A fragments, one per ks

    #pragma unroll
    for (int t = 0; t < NT; ++t) {
        // wait for slab t (pending groups may keep: t+1..min(t+2,7))
        if (t < 6) cpa_wait<2>(); else if (t == 6) cpa_wait<1>(); else cpa_wait<0>();
        __syncthreads();   // publishes slab t; proves tile t-1 reads done

        if (t + 3 < NT) pfB(t + 3);   // buf (t-1)&3, safe after barrier

        if (t == 0) {
            #pragma unroll
            for (int ks = 0; ks < 8; ++ks) {
                uint32_t ac = (uint32_t)((((2 * ks + amc) ^ ax7) & 15) << 4);
                ldsm4(afrag[ks], sb + OFF_A + arow256 + ac);
            }
        }

        const uint32_t Bh = sb + OFF_B + (t & 3) * BBUF;

        // register-double-buffered B fragment pipeline over ks
        uint32_t bcur[4], bnxt[4];
        {
            uint32_t bc0 = (uint32_t)(((bmc ^ bx7) & 15) << 4);
            ldsm4(bcur, Bh + brow256 + bc0);
        }
        #pragma unroll
        for (int ks = 0; ks < 8; ++ks) {
            if (ks < 7) {
                uint32_t bcn = (uint32_t)((((2 * (ks + 1) + bmc) ^ bx7) & 15) << 4);
                ldsm4(bnxt, Bh + brow256 + bcn);
            }
            mma16816(&acc[t][0], afrag[ks], bcur[0], bcur[1]);
            mma16816(&acc[t][4], afrag[ks], bcur[2], bcur[3]);
            #pragma unroll
            for (int z = 0; z < 4; ++z) bcur[z] = bnxt[z];
        }

        // exp for tile t (acc[t] final) — fills idle issue slots
        #pragma unroll
        for (int j = 0; j < 8; ++j) acc[t][j] = __expf(sc * acc[t][j]);
    }

    // ---- row sums (rows wb*16 + lane/4 and +8) ----
    float s0 = 0.0f, s1 = 0.0f;
    #pragma unroll
    for (int t = 0; t < NT; ++t) {
        s0 += (acc[t][0] + acc[t][1]) + (acc[t][4] + acc[t][5]);
        s1 += (acc[t][2] + acc[t][3]) + (acc[t][6] + acc[t][7]);
    }
    #pragma unroll
    for (int o = 1; o < 4; o <<= 1) {
        s0 += __shfl_xor_sync(0xFFFFFFFFu, s0, o);
        s1 += __shfl_xor_sync(0xFFFFFFFFu, s1, o);
    }
    float* rs  = (float*)(smem + OFF_RS);
    float* inv = (float*)(smem + OFF_INV);
    const int g8 = lane >> 2;
    if ((lane & 3) == 0) {
        rs[wc * 32 + wb * 16 + g8]     = s0;
        rs[wc * 32 + wb * 16 + 8 + g8] = s1;
    }
    __syncthreads();
    if (tid < 32) {
        float tot = 0.0f;
        #pragma unroll
        for (int cb = 0; cb < 8; ++cb) tot += rs[cb * 32 + tid];
        inv[tid] = 1.0f / tot;
    }
    __syncthreads();
    const float i0 = inv[wb * 16 + g8];
    const float i1 = inv[wb * 16 + 8 + g8];

    // ---- normalized stores ----
    const int r0 = mtile * BM + wb * 16 + g8;
    float* ob0 = out + ((size_t)bh * Pp + r0) * Pp + wc * 16 + 2 * (lane & 3);
    float* ob1 = ob0 + 8ull * Pp;
    #pragma unroll
    for (int t = 0; t < NT; ++t) {
        int c0 = t * TN;
        float2 v;
        v.x = acc[t][0] * i0; v.y = acc[t][1] * i0; *(float2*)(ob0 + c0)     = v;
        v.x = acc[t][2] * i1; v.y = acc[t][3] * i1; *(float2*)(ob1 + c0)     = v;
        v.x = acc[t][4] * i0; v.y = acc[t][5] * i0; *(float2*)(ob0 + c0 + 8) = v;
        v.x = acc[t][6] * i1; v.y = acc[t][7] * i1; *(float2*)(ob1 + c0 + 8) = v;
    }
}

// =================== launch ===================
extern "C" void kernel_launch(void* const* d_in, const int* in_sizes, int n_in,
                              void* d_out, int out_size)
{
    const float* q     = (const float*)d_in[0];
    const float* k     = (const float*)d_in[1];
    const float* scale = (const float*)d_in[2];
    float* out = (float*)d_out;

    silu_split_kernel<<<NELEM / 4 / 256, 256>>>(q, k);

    cudaFuncSetAttribute(attn_mma_kernel,
                         cudaFuncAttributeMaxDynamicSharedMemorySize, SMEM2);
    dim3 grid(Pp / BM, Bc * Hc);  // (32, 64)
    attn_mma_kernel<<<grid, 512, SMEM2>>>(scale, out);
}

// round 8
// speedup vs baseline: 2.3677x; 1.0496x over previous
#include <cuda_runtime.h>
#include <cuda_fp16.h>
#include <stdint.h>

constexpr int Bc = 4, Hc = 16, Pp = 1024, Dd = 128;
constexpr int NELEM = Bc * Hc * Pp * Dd;   // 8388608
constexpr int BM = 32;       // query rows per CTA
constexpr int TN = 128;      // keys per tile
constexpr int NT = Pp / TN;  // 8 tiles

// ---- device scratch: silu'd q, k as fp16 ----
__device__ __half g_qh[NELEM], g_kh[NELEM];

// ---- smem layout (bytes) ----
constexpr int OFF_A   = 0;          // 32 rows x 256B (swizzled)
constexpr int OFF_B   = 8192;       // 8 wc x 4 slots x 4KB = 128KB
constexpr int SLAB    = 4096;       // 16 keys x 256B
constexpr int OFF_RS  = OFF_B + 8 * 4 * SLAB;   // 139264
constexpr int OFF_INV = OFF_RS + 2048;
constexpr int SMEM2   = OFF_INV + 128;          // 141440 B

// =================== helpers ===================
__device__ __forceinline__ uint32_t smem_u32(const void* p) {
    uint32_t a;
    asm("{ .reg .u64 t; cvta.to.shared.u64 t, %1; cvt.u32.u64 %0, t; }" : "=r"(a) : "l"(p));
    return a;
}
__device__ __forceinline__ void cpa16(uint32_t dst, const void* src) {
    asm volatile("cp.async.cg.shared.global [%0], [%1], 16;" :: "r"(dst), "l"(src));
}
__device__ __forceinline__ void cpa_commit() { asm volatile("cp.async.commit_group;" ::: "memory"); }
template<int N>
__device__ __forceinline__ void cpa_wait() { asm volatile("cp.async.wait_group %0;" :: "n"(N) : "memory"); }
__device__ __forceinline__ void bar_pair(int id) {
    asm volatile("bar.sync %0, 64;" :: "r"(id) : "memory");
}

__device__ __forceinline__ void ldsm4(uint32_t* r, uint32_t addr) {
    asm volatile("ldmatrix.sync.aligned.m8n8.x4.shared.b16 {%0,%1,%2,%3}, [%4];"
                 : "=r"(r[0]), "=r"(r[1]), "=r"(r[2]), "=r"(r[3]) : "r"(addr));
}
__device__ __forceinline__ void mma16816(float* d, const uint32_t* a, uint32_t b0, uint32_t b1) {
    asm volatile(
        "mma.sync.aligned.m16n8k16.row.col.f32.f16.f16.f32 "
        "{%0,%1,%2,%3}, {%4,%5,%6,%7}, {%8,%9}, {%0,%1,%2,%3};"
        : "+f"(d[0]), "+f"(d[1]), "+f"(d[2]), "+f"(d[3])
        : "r"(a[0]), "r"(a[1]), "r"(a[2]), "r"(a[3]), "r"(b0), "r"(b1));
}
__device__ __forceinline__ float silu_f(float x) {
    return x * (1.0f / (1.0f + __expf(-x)));
}
__device__ __forceinline__ uint32_t pack_h2(__half a, __half b) {
    __half2 t(a, b);
    return *reinterpret_cast<uint32_t*>(&t);
}

// =================== Pass 1: silu -> fp16 ===================
__global__ void __launch_bounds__(256)
silu_split_kernel(const float* __restrict__ q, const float* __restrict__ k)
{
    int j = blockIdx.x * 256 + threadIdx.x;
    float4 vq = ((const float4*)q)[j];
    float4 vk = ((const float4*)k)[j];

    ((uint2*)g_qh)[j] = make_uint2(
        pack_h2(__float2half(silu_f(vq.x)), __float2half(silu_f(vq.y))),
        pack_h2(__float2half(silu_f(vq.z)), __float2half(silu_f(vq.w))));
    ((uint2*)g_kh)[j] = make_uint2(
        pack_h2(__float2half(silu_f(vk.x)), __float2half(silu_f(vk.y))),
        pack_h2(__float2half(silu_f(vk.z)), __float2half(silu_f(vk.w))));
}

// =================== Pass 2: HMMA GEMM + fused softmax ===================
// 512 threads = 16 warps = 8 independent pair-pipelines. Pair wc owns keys
// [wc*16, wc*16+16) of every tile in a private 4-slot slab ring; wb0 loads
// even tiles, wb1 odd. Pair-scoped named barriers replace CTA lockstep.
__global__ void __launch_bounds__(512, 1)
attn_mma_kernel(const float* __restrict__ scale_p, float* __restrict__ out)
{
    extern __shared__ char smem[];
    const uint32_t sb = smem_u32(smem);
    const int tid = threadIdx.x, lane = tid & 31, w = tid >> 5;
    const int wb = w & 1, wc = w >> 1;
    const int mtile = blockIdx.x, bh = blockIdx.y;
    const float sc = scale_p[0];

    // ---- A tile (32 rows x 128 fp16), swizzled 16B chunks: group 1 (all threads) ----
    {
        int row = tid >> 4, c = tid & 15;
        size_t g = ((size_t)(bh * Pp + mtile * BM) + row) * 256 + c * 16;
        uint32_t off = row * 256 + (((c ^ (row & 7)) & 15) << 4);
        cpa16(sb + OFF_A + off, (const char*)g_qh + g);
    }
    cpa_commit();

    const char* khB = (const char*)g_kh + (size_t)bh * Pp * 256;
    const uint32_t myring = sb + OFF_B + (uint32_t)wc * (4 * SLAB);

    // slab load: 16 keys x 256B for pair wc, tile t -> slot t&3 (one warp)
    auto pfSlab = [&](int t) {
        uint32_t dst = myring + (uint32_t)(t & 3) * SLAB;
        const char* src = khB + (size_t)(t * TN + wc * 16) * 256;
        #pragma unroll
        for (int i = 0; i < 8; ++i) {
            int idx = lane + (i << 5);           // 0..255
            int key = idx >> 4, c = idx & 15;
            uint32_t off = (uint32_t)(key * 256) + (((c ^ (key & 7)) & 15) << 4);
            cpa16(dst + off, src + idx * 16);
        }
        cpa_commit();
    };
    // prologue: fill 4 slots. wb0: tiles 0,2 (groups 2,3); wb1: tiles 1,3.
    pfSlab(wb);        // t = wb
    pfSlab(wb + 2);    // t = wb+2

    cpa_wait<2>();      // group 1 (A) complete for every thread
    __syncthreads();    // A visible CTA-wide; slab rings privately tracked below

    // ---- fragment addressing ----
    const int lm = lane >> 3, lr = lane & 7;
    const int arow = wb * 16 + ((lm & 1) << 3) + lr;
    const uint32_t arow256 = (uint32_t)arow * 256;
    const int ax7 = arow & 7, amc = lm >> 1;
    const int brow = ((lm >> 1) << 3) + lr;          // local key row 0..15
    const uint32_t brow256 = (uint32_t)brow * 256;
    const int bx7 = brow & 7, bmc = lm & 1;
    const int barid = 1 + wc;

    uint32_t afrag[8][4];
    #pragma unroll
    for (int ks = 0; ks < 8; ++ks) {
        uint32_t ac = (uint32_t)((((2 * ks + amc) ^ ax7) & 15) << 4);
        ldsm4(afrag[ks], sb + OFF_A + arow256 + ac);
    }

    float acc[NT][8];
    #pragma unroll
    for (int t = 0; t < NT; ++t)
        #pragma unroll
        for (int j = 0; j < 8; ++j) acc[t][j] = 0.0f;

    #pragma unroll
    for (int t = 0; t < NT; ++t) {
        // loader waits for its own group carrying slab t
        if (wb == (t & 1)) {
            if (t < 6) cpa_wait<1>(); else cpa_wait<0>();
        }
        bar_pair(barid);   // slab t visible to both warps of the pair

        const uint32_t Bh = myring + (uint32_t)(t & 3) * SLAB;

        uint32_t bcur[4], bnxt[4];
        {
            uint32_t bc0 = (uint32_t)(((bmc ^ bx7) & 15) << 4);
            ldsm4(bcur, Bh + brow256 + bc0);
        }
        #pragma unroll
        for (int ks = 0; ks < 8; ++ks) {
            if (ks < 7) {
                uint32_t bcn = (uint32_t)((((2 * (ks + 1) + bmc) ^ bx7) & 15) << 4);
                ldsm4(bnxt, Bh + brow256 + bcn);
            }
            mma16816(&acc[t][0], afrag[ks], bcur[0], bcur[1]);
            mma16816(&acc[t][4], afrag[ks], bcur[2], bcur[3]);
            #pragma unroll
            for (int z = 0; z < 4; ++z) bcur[z] = bnxt[z];
        }

        // exp for tile t while waiting
        #pragma unroll
        for (int j = 0; j < 8; ++j) acc[t][j] = __expf(sc * acc[t][j]);

        bar_pair(barid);   // both warps done reading slot t&3
        if (t + 4 < NT && wb == (t & 1)) pfSlab(t + 4);   // reuse slot (t&3)
    }

    // ---- row sums (rows wb*16 + lane/4 and +8) ----
    float s0 = 0.0f, s1 = 0.0f;
    #pragma unroll
    for (int t = 0; t < NT; ++t) {
        s0 += (acc[t][0] + acc[t][1]) + (acc[t][4] + acc[t][5]);
        s1 += (acc[t][2] + acc[t][3]) + (acc[t][6] + acc[t][7]);
    }
    #pragma unroll
    for (int o = 1; o < 4; o <<= 1) {
        s0 += __shfl_xor_sync(0xFFFFFFFFu, s0, o);
        s1 += __shfl_xor_sync(0xFFFFFFFFu, s1, o);
    }
    float* rs  = (float*)(smem + OFF_RS);
    float* inv = (float*)(smem + OFF_INV);
    const int g8 = lane >> 2;
    if ((lane & 3) == 0) {
        rs[wc * 32 + wb * 16 + g8]     = s0;
        rs[wc * 32 + wb * 16 + 8 + g8] = s1;
    }
    __syncthreads();
    if (tid < 32) {
        float tot = 0.0f;
        #pragma unroll
        for (int cb = 0; cb < 8; ++cb) tot += rs[cb * 32 + tid];
        inv[tid] = 1.0f / tot;
    }
    __syncthreads();
    const float i0 = inv[wb * 16 + g8];
    const float i1 = inv[wb * 16 + 8 + g8];

    // ---- normalized stores ----
    const int r0 = mtile * BM + wb * 16 + g8;
    float* ob0 = out + ((size_t)bh * Pp + r0) * Pp + wc * 16 + 2 * (lane & 3);
    float* ob1 = ob0 + 8ull * Pp;
    #pragma unroll
    for (int t = 0; t < NT; ++t) {
        int c0 = t * TN;
        float2 v;
        v.x = acc[t][0] * i0; v.y = acc[t][1] * i0; *(float2*)(ob0 + c0)     = v;
        v.x = acc[t][2] * i1; v.y = acc[t][3] * i1; *(float2*)(ob1 + c0)     = v;
        v.x = acc[t][4] * i0; v.y = acc[t][5] * i0; *(float2*)(ob0 + c0 + 8) = v;
        v.x = acc[t][6] * i1; v.y = acc[t][7] * i1; *(float2*)(ob1 + c0 + 8) = v;
    }
}

// =================== launch ===================
extern "C" void kernel_launch(void* const* d_in, const int* in_sizes, int n_in,
                              void* d_out, int out_size)
{
    const float* q     = (const float*)d_in[0];
    const float* k     = (const float*)d_in[1];
    const float* scale = (const float*)d_in[2];
    float* out = (float*)d_out;

    silu_split_kernel<<<NELEM / 4 / 256, 256>>>(q, k);

    cudaFuncSetAttribute(attn_mma_kernel,
                         cudaFuncAttributeMaxDynamicSharedMemorySize, SMEM2);
    dim3 grid(Pp / BM, Bc * Hc);  // (32, 64)
    attn_mma_kernel<<<grid, 512, SMEM2>>>(scale, out);
}

// round 9
// speedup vs baseline: 2.3700x; 1.0010x over previous
#include <cuda_runtime.h>
#include <cuda_fp16.h>
#include <stdint.h>

constexpr int Bc = 4, Hc = 16, Pp = 1024, Dd = 128;
constexpr int NELEM = Bc * Hc * Pp * Dd;   // 8388608
constexpr int BM = 32;       // query rows per CTA
constexpr int TN = 128;      // keys per tile
constexpr int NT = Pp / TN;  // 8 tiles

// ---- device scratch: silu'd q, k as fp16 ----
__device__ __half g_qh[NELEM], g_kh[NELEM];

// ---- smem layout (bytes) ----
constexpr int OFF_Q   = 0;        // 32 rows x 256B (swizzled) = 8192
constexpr int OFF_K   = 8192;     // 16 warps x 4 slots x 2KB = 131072
constexpr int OFF_SC  = 139264;   // 32 rows x 2048B fp16 scores = 65536
constexpr int OFF_RS  = 204800;   // 16 warps x 32 rows x 4B = 2048
constexpr int OFF_INV = 206848;   // 32 x 4B
constexpr int SMEM2   = 206976;

// =================== helpers ===================
__device__ __forceinline__ uint32_t smem_u32(const void* p) {
    uint32_t a;
    asm("{ .reg .u64 t; cvta.to.shared.u64 t, %1; cvt.u32.u64 %0, t; }" : "=r"(a) : "l"(p));
    return a;
}
__device__ __forceinline__ void cpa16(uint32_t dst, const void* src) {
    asm volatile("cp.async.cg.shared.global [%0], [%1], 16;" :: "r"(dst), "l"(src));
}
__device__ __forceinline__ void cpa_commit() { asm volatile("cp.async.commit_group;" ::: "memory"); }
template<int N>
__device__ __forceinline__ void cpa_wait() { asm volatile("cp.async.wait_group %0;" :: "n"(N) : "memory"); }

__device__ __forceinline__ void ldsm4(uint32_t* r, uint32_t addr) {
    asm volatile("ldmatrix.sync.aligned.m8n8.x4.shared.b16 {%0,%1,%2,%3}, [%4];"
                 : "=r"(r[0]), "=r"(r[1]), "=r"(r[2]), "=r"(r[3]) : "r"(addr));
}
__device__ __forceinline__ void ldsm2(uint32_t* r, uint32_t addr) {
    asm volatile("ldmatrix.sync.aligned.m8n8.x2.shared.b16 {%0,%1}, [%2];"
                 : "=r"(r[0]), "=r"(r[1]) : "r"(addr));
}
__device__ __forceinline__ void mma16816(float* d, const uint32_t* a, uint32_t b0, uint32_t b1) {
    asm volatile(
        "mma.sync.aligned.m16n8k16.row.col.f32.f16.f16.f32 "
        "{%0,%1,%2,%3}, {%4,%5,%6,%7}, {%8,%9}, {%0,%1,%2,%3};"
        : "+f"(d[0]), "+f"(d[1]), "+f"(d[2]), "+f"(d[3])
        : "r"(a[0]), "r"(a[1]), "r"(a[2]), "r"(a[3]), "r"(b0), "r"(b1));
}
__device__ __forceinline__ void sts32(uint32_t addr, uint32_t v) {
    asm volatile("st.shared.u32 [%0], %1;" :: "r"(addr), "r"(v) : "memory");
}
__device__ __forceinline__ void lds64(uint32_t& a, uint32_t& b, uint32_t addr) {
    asm volatile("ld.shared.v2.u32 {%0,%1}, [%2];" : "=r"(a), "=r"(b) : "r"(addr));
}
__device__ __forceinline__ float silu_f(float x) {
    return x * (1.0f / (1.0f + __expf(-x)));
}
__device__ __forceinline__ uint32_t pack_h2(__half a, __half b) {
    __half2 t(a, b);
    return *reinterpret_cast<uint32_t*>(&t);
}
__device__ __forceinline__ uint32_t f2h2(float a, float b) {
    __half2 t = __floats2half2_rn(a, b);
    return *reinterpret_cast<uint32_t*>(&t);
}

// =================== Pass 1: silu -> fp16 ===================
__global__ void __launch_bounds__(256)
silu_split_kernel(const float* __restrict__ q, const float* __restrict__ k)
{
    int j = blockIdx.x * 256 + threadIdx.x;
    float4 vq = ((const float4*)q)[j];
    float4 vk = ((const float4*)k)[j];

    ((uint2*)g_qh)[j] = make_uint2(
        pack_h2(__float2half(silu_f(vq.x)), __float2half(silu_f(vq.y))),
        pack_h2(__float2half(silu_f(vq.z)), __float2half(silu_f(vq.w))));
    ((uint2*)g_kh)[j] = make_uint2(
        pack_h2(__float2half(silu_f(vk.x)), __float2half(silu_f(vk.y))),
        pack_h2(__float2half(silu_f(vk.z)), __float2half(silu_f(vk.w))));
}

// =================== Pass 2: HMMA GEMM + fused softmax ===================
// 512 threads = 16 fully independent warps. Warp w owns ALL 32 rows x keys
// [t*128 + w*8, +8) of every tile t. Q hoisted to 64 regs; K in a warp-private
// 4-slot cp.async ring (no mainloop barriers). exp'd scores staged fp16 in
// smem; final phase does coalesced normalize+store.
__global__ void __launch_bounds__(512, 1)
attn_mma_kernel(const float* __restrict__ scale_p, float* __restrict__ out)
{
    extern __shared__ char smem[];
    const uint32_t sb = smem_u32(smem);
    const int tid = threadIdx.x, lane = tid & 31, w = tid >> 5;
    const int mtile = blockIdx.x, bh = blockIdx.y;
    const float sc = scale_p[0];

    // ---- Q tile load (32 rows x 128 fp16), swizzled 16B chunks: group 0 ----
    {
        int row = tid >> 4, c = tid & 15;
        size_t g = ((size_t)(bh * Pp + mtile * BM) + row) * 256 + c * 16;
        uint32_t off = row * 256 + (((c ^ (row & 7)) & 15) << 4);
        cpa16(sb + OFF_Q + off, (const char*)g_qh + g);
    }
    cpa_commit();

    const char* khB = (const char*)g_kh + (size_t)bh * Pp * 256;
    const uint32_t myring = sb + OFF_K + (uint32_t)w * 8192;

    // warp-private slab: 8 keys x 256B for tile t -> slot t&3
    auto pfK = [&](int t) {
        uint32_t dst = myring + (uint32_t)(t & 3) * 2048;
        const char* src = khB + (size_t)(t * TN + w * 8) * 256;
        #pragma unroll
        for (int i = 0; i < 4; ++i) {
            int idx = lane + (i << 5);           // 0..127
            int key = idx >> 4, c = idx & 15;
            uint32_t off = (uint32_t)(key * 256) + (((c ^ (key & 7)) & 15) << 4);
            cpa16(dst + off, src + key * 256 + c * 16);
        }
        cpa_commit();
    };
    pfK(0); pfK(1); pfK(2); pfK(3);   // groups 1..4

    cpa_wait<4>();      // Q (group 0) retired
    __syncthreads();    // Q visible to all warps

    // ---- hoist Q fragments (2 row-groups x 8 ks) ----
    const int lm = lane >> 3, lr = lane & 7;
    uint32_t aq[2][8][4];
    #pragma unroll
    for (int rg = 0; rg < 2; ++rg) {
        int arow = rg * 16 + ((lm & 1) << 3) + lr;
        uint32_t arow256 = (uint32_t)arow * 256;
        int ax7 = arow & 7, amc = lm >> 1;
        #pragma unroll
        for (int ks = 0; ks < 8; ++ks) {
            uint32_t ac = (uint32_t)((((2 * ks + amc) ^ ax7) & 15) << 4);
            ldsm4(aq[rg][ks], sb + OFF_Q + arow256 + ac);
        }
    }

    // B addressing (lanes 0-15 meaningful for ldsm.x2)
    const int brow = lane & 7;
    const int bsel = (lane >> 3) & 1;
    const uint32_t browoff = (uint32_t)brow * 256;
    const int r0 = lane >> 2;                       // 0..7
    const uint32_t rx = (uint32_t)((r0 & 7) << 4);  // score swizzle for this thread's rows
    const uint32_t kcolbyte = (uint32_t)(w * 16 + 4 * (lane & 3));
    const uint32_t scb = sb + OFF_SC;

    float s[4] = {0.f, 0.f, 0.f, 0.f};

    #pragma unroll
    for (int t = 0; t < NT; ++t) {
        // per-warp wait for slab t (no CTA barrier)
        if (t <= 4) cpa_wait<3>();
        else if (t == 5) cpa_wait<2>();
        else if (t == 6) cpa_wait<1>();
        else cpa_wait<0>();

        const uint32_t Kb = myring + (uint32_t)(t & 3) * 2048;
        float acc0[4] = {0.f, 0.f, 0.f, 0.f};
        float acc1[4] = {0.f, 0.f, 0.f, 0.f};

        #pragma unroll
        for (int ks = 0; ks < 8; ++ks) {
            uint32_t b2[2];
            uint32_t bc = (uint32_t)((((2 * ks + bsel) ^ brow) & 15) << 4);
            ldsm2(b2, Kb + browoff + bc);
            mma16816(acc0, aq[0][ks], b2[0], b2[1]);
            mma16816(acc1, aq[1][ks], b2[0], b2[1]);
        }

        if (t + 4 < NT) pfK(t + 4);   // refill slot t&3 (warp-private, reads done)

        // exp + fp32 sums + fp16 pack + swizzled STS
        uint32_t kb = (uint32_t)t * 256 + kcolbyte;
        float e0, e1;
        e0 = __expf(sc * acc0[0]); e1 = __expf(sc * acc0[1]); s[0] += e0 + e1;
        sts32(scb + (uint32_t)r0 * 2048        + (kb ^ rx), f2h2(e0, e1));
        e0 = __expf(sc * acc0[2]); e1 = __expf(sc * acc0[3]); s[1] += e0 + e1;
        sts32(scb + (uint32_t)(r0 + 8) * 2048  + (kb ^ rx), f2h2(e0, e1));
        e0 = __expf(sc * acc1[0]); e1 = __expf(sc * acc1[1]); s[2] += e0 + e1;
        sts32(scb + (uint32_t)(r0 + 16) * 2048 + (kb ^ rx), f2h2(e0, e1));
        e0 = __expf(sc * acc1[2]); e1 = __expf(sc * acc1[3]); s[3] += e0 + e1;
        sts32(scb + (uint32_t)(r0 + 24) * 2048 + (kb ^ rx), f2h2(e0, e1));
    }

    // ---- row sums: reduce over key-lanes (lane&3), then over warps ----
    #pragma unroll
    for (int o = 1; o < 4; o <<= 1) {
        s[0] += __shfl_xor_sync(0xFFFFFFFFu, s[0], o);
        s[1] += __shfl_xor_sync(0xFFFFFFFFu, s[1], o);
        s[2] += __shfl_xor_sync(0xFFFFFFFFu, s[2], o);
        s[3] += __shfl_xor_sync(0xFFFFFFFFu, s[3], o);
    }
    float* rs  = (float*)(smem + OFF_RS);
    float* inv = (float*)(smem + OFF_INV);
    if ((lane & 3) == 0) {
        rs[w * 32 + r0]      = s[0];
        rs[w * 32 + r0 + 8]  = s[1];
        rs[w * 32 + r0 + 16] = s[2];
        rs[w * 32 + r0 + 24] = s[3];
    }
    __syncthreads();   // also publishes all score STS
    if (tid < 32) {
        float tot = 0.0f;
        #pragma unroll
        for (int ww = 0; ww < 16; ++ww) tot += rs[ww * 32 + tid];
        inv[tid] = 1.0f / tot;
    }
    __syncthreads();

    // ---- coalesced normalize + store ----
    const int row = tid >> 4, cc = tid & 15;
    const float iv = inv[row];
    float* orow = out + ((size_t)bh * Pp + mtile * BM + row) * Pp;
    const uint32_t rbase = scb + (uint32_t)row * 2048;
    const uint32_t rxr = (uint32_t)((row & 7) << 4);
    #pragma unroll
    for (int p = 0; p < 16; ++p) {
        int key = cc * 4 + p * 64;
        uint32_t a, b;
        lds64(a, b, rbase + (((uint32_t)(key * 2)) ^ rxr));
        __half2 ha = *reinterpret_cast<__half2*>(&a);
        __half2 hb = *reinterpret_cast<__half2*>(&b);
        float2 fa = __half22float2(ha);
        float2 fb = __half22float2(hb);
        float4 v = make_float4(fa.x * iv, fa.y * iv, fb.x * iv, fb.y * iv);
        *(float4*)(orow + key) = v;
    }
}

// =================== launch ===================
extern "C" void kernel_launch(void* const* d_in, const int* in_sizes, int n_in,
                              void* d_out, int out_size)
{
    const float* q     = (const float*)d_in[0];
    const float* k     = (const float*)d_in[1];
    const float* scale = (const float*)d_in[2];
    float* out = (float*)d_out;

    silu_split_kernel<<<NELEM / 4 / 256, 256>>>(q, k);

    cudaFuncSetAttribute(attn_mma_kernel,
                         cudaFuncAttributeMaxDynamicSharedMemorySize, SMEM2);
    dim3 grid(Pp / BM, Bc * Hc);  // (32, 64)
    attn_mma_kernel<<<grid, 512, SMEM2>>>(scale, out);
}